// round 17
// baseline (speedup 1.0000x reference)
#include <cuda_runtime.h>
#include <math.h>
#include <stdint.h>

#define BB      2
#define FRAMES  4
#define LSEQ    784
#define NT      1568
#define DM      256
#define DI      512
#define DSTATE  16
#define DTR     16
#define NDEPTH  12
#define NPATCH  196
#define KPATCH  768
#define NCHUNK  7
#define CLEN    112
#define NGRP    (2 * BB * DI * DSTATE)

// ---------------- scratch ----------------
__device__ float g_im2col[NT * KPATCH];
__device__ float g_hidden[NT * DM];
__device__ float g_resid [NT * DM];
__device__ float g_scale [NT];
__device__ float g_xz    [NT * 2 * DI];
__device__ float g_xs    [2 * DI * NT];   // TRANSPOSED: [dir][d][b*784+t]
__device__ float g_gz    [DI * NT];       // TRANSPOSED silu(z)
__device__ float g_dbl   [2 * NT * 48];
__device__ float g_dt    [2 * DI * NT];   // TRANSPOSED
__device__ float g_y     [2 * DI * NT];   // TRANSPOSED
__device__ float g_A     [2 * NDEPTH * DI * DSTATE];
__device__ float g_P     [NCHUNK][NGRP];
__device__ float g_q     [NCHUNK][NGRP];

static __device__ __forceinline__ float siluf(float x) {
    return x / (1.f + __expf(-x));
}
static __device__ __forceinline__ float softplusf(float x) {
    return (x > 20.f) ? x : log1pf(__expf(x));
}
static __device__ __forceinline__ uint32_t f2tf32(float x) {
    uint32_t r;
    asm("cvt.rna.tf32.f32 %0, %1;" : "=r"(r) : "f"(x));
    return r;
}
static __device__ __forceinline__ void mma_tf32(float* d, const uint32_t* a, const uint32_t* b) {
    asm volatile(
        "mma.sync.aligned.m16n8k8.row.col.f32.tf32.tf32.f32 "
        "{%0,%1,%2,%3}, {%4,%5,%6,%7}, {%8,%9}, {%0,%1,%2,%3};"
        : "+f"(d[0]), "+f"(d[1]), "+f"(d[2]), "+f"(d[3])
        : "r"(a[0]), "r"(a[1]), "r"(a[2]), "r"(a[3]), "r"(b[0]), "r"(b[1]));
}

// im2col + zero g_hidden + prep A (folded)
__global__ void im2col_kernel(const float* __restrict__ x,
                              const float* __restrict__ Af,
                              const float* __restrict__ Ab) {
    int e = blockIdx.x * blockDim.x + threadIdx.x;
    if (e >= NT * KPATCH) return;
    if (e < NT * DM) g_hidden[e] = 0.f;
    const int NA = NDEPTH * DI * DSTATE;
    if (e < NA) {
        g_A[e]      = -expf(Af[e]);
        g_A[NA + e] = -expf(Ab[e]);
    }
    int n = e / KPATCH, k = e % KPATCH;
    int b = n / LSEQ, tl = n % LSEQ;
    int t = tl / NPATCH, p = tl % NPATCH;
    int ph = p / 14, pw = p % 14;
    int ci = k / 256, rem = k % 256;
    int ii = rem / 16, jj = rem % 16;
    long off = (((long)(b * 3 + ci) * FRAMES + t) * 224 + (ph * 16 + ii)) * 224 + (pw * 16 + jj);
    g_im2col[e] = x[off];
}

// ---------------- TF32 tensor-core GEMM, 64x64 tile, 4 warps ------------------
// C[M,N] = (A [+A2]) @ W^T ; W is N x K row-major. z = dir*SK + ks.
// TRANSA: A col-major A[k*lda + row]. TRANSC: C written transposed, smem-staged.
// ANORM: A element scaled by g_scale[row]*nw[k] (fused rmsnorm for in_proj).
// EPI: 0 none, 1 softplus(+bias), 2 patch epilogue (ks==0 only).
// All row/col base pointers are hoisted; per-tile address math is a 32-bit add.
#define TBM  64
#define TBN  64
#define TBK  16
#define TBKP 20
template <int EPI, bool ATOMIC, bool TRANSA, bool TRANSC, bool ANORM>
__global__ void __launch_bounds__(128, 8)
mma_gemm_kernel(const float* __restrict__ A, const float* __restrict__ A2, int lda,
                const float* __restrict__ W, const float* __restrict__ Wb,
                float* __restrict__ C, int ldc,
                int M, int N, int K, int SK,
                const float* __restrict__ bias, const float* __restrict__ biasb,
                const float* __restrict__ pos, const float* __restrict__ temp,
                long strideA, long strideC,
                const float* __restrict__ nw) {
    __shared__ uint32_t As[2][TBM][TBKP];
    __shared__ uint32_t Bs[2][TBN][TBKP];

    int z = blockIdx.z;
    int dir = z / SK, ks = z - dir * SK;
    if (dir) { A += strideA; C += strideC; W = Wb; bias = biasb; if (A2) A2 += strideA; }
    int Kc = K / SK;
    int kbase = ks * Kc;
    int nk = Kc / TBK;

    int tid = threadIdx.x;
    int lane = tid & 31;
    int wid = tid >> 5;
    int wm = wid >> 1, wn = wid & 1;
    int qr = lane >> 2, qc = lane & 3;

    int rowBase = blockIdx.y * TBM;
    int colBase = blockIdx.x * TBN;

    int lr = tid >> 1;
    int lc8 = (tid & 1) * 8;

    // ---- hoisted base pointers & predicates ----
    bool rowOK = false, t0ok = false, t1ok = false;
    int t0r4 = 0, t1r4 = 0;
    const float *pA = nullptr, *pA2 = nullptr;
    const float *pT0A = nullptr, *pT0A2 = nullptr, *pT1A = nullptr, *pT1A2 = nullptr;
    const float *pNW = nullptr;
    float rowsc = 1.f;

    if (TRANSA) {
        int item0 = tid, item1 = 128 + tid;
        int t0kk = item0 >> 4; t0r4 = (item0 & 15) * 4;
        int t1kk = item1 >> 4; t1r4 = (item1 & 15) * 4;
        t0ok = (rowBase + t0r4) < M;
        t1ok = (rowBase + t1r4) < M;
        pT0A = A + (long)(kbase + t0kk) * lda + rowBase + t0r4;
        pT1A = A + (long)(kbase + t1kk) * lda + rowBase + t1r4;
        if (A2) {
            pT0A2 = A2 + (long)(kbase + t0kk) * lda + rowBase + t0r4;
            pT1A2 = A2 + (long)(kbase + t1kk) * lda + rowBase + t1r4;
        }
    } else {
        rowOK = (rowBase + lr) < M;
        pA = A + (long)(rowBase + lr) * lda + kbase + lc8;
        if (A2) pA2 = A2 + (long)(rowBase + lr) * lda + kbase + lc8;
        if (ANORM) {
            int r = rowBase + lr;
            rowsc = (r < M) ? g_scale[r] : 0.f;
            pNW = nw + kbase + lc8;
        }
    }
    bool colOK = (colBase + lr) < N;
    const float* pW = W + (long)(colBase + lr) * K + kbase + lc8;
    const long tStepA = (long)TBK * lda;   // TRANSA per-tile pointer step

    // koff: element offset of current tile relative to the hoisted base
    auto load_tile = [&](int koff, int buf) {
        if (TRANSA) {
            {
                float4 v = make_float4(0.f, 0.f, 0.f, 0.f);
                if (t0ok) {
                    const float* p = pT0A + (long)(koff >> 4) * tStepA / TBK * TBK; // koff is multiple of TBK
                    // simpler: advance via precomputed multiple below
                    p = pT0A + (koff / TBK) * tStepA;
                    v = *(const float4*)p;
                    if (A2) {
                        const float* p2 = pT0A2 + (koff / TBK) * tStepA;
                        float4 w = *(const float4*)p2;
                        v.x += w.x; v.y += w.y; v.z += w.z; v.w += w.w;
                    }
                }
                int kk = tid >> 4;
                As[buf][t0r4 + 0][kk] = f2tf32(v.x);
                As[buf][t0r4 + 1][kk] = f2tf32(v.y);
                As[buf][t0r4 + 2][kk] = f2tf32(v.z);
                As[buf][t0r4 + 3][kk] = f2tf32(v.w);
            }
            {
                float4 v = make_float4(0.f, 0.f, 0.f, 0.f);
                if (t1ok) {
                    const float* p = pT1A + (koff / TBK) * tStepA;
                    v = *(const float4*)p;
                    if (A2) {
                        const float* p2 = pT1A2 + (koff / TBK) * tStepA;
                        float4 w = *(const float4*)p2;
                        v.x += w.x; v.y += w.y; v.z += w.z; v.w += w.w;
                    }
                }
                int kk = (128 + tid) >> 4;
                As[buf][t1r4 + 0][kk] = f2tf32(v.x);
                As[buf][t1r4 + 1][kk] = f2tf32(v.y);
                As[buf][t1r4 + 2][kk] = f2tf32(v.z);
                As[buf][t1r4 + 3][kk] = f2tf32(v.w);
            }
        } else {
            float4 a0 = make_float4(0.f, 0.f, 0.f, 0.f);
            float4 a1 = make_float4(0.f, 0.f, 0.f, 0.f);
            if (rowOK) {
                a0 = *(const float4*)(pA + koff);
                a1 = *(const float4*)(pA + koff + 4);
                if (A2) {
                    float4 w0 = *(const float4*)(pA2 + koff);
                    float4 w1 = *(const float4*)(pA2 + koff + 4);
                    a0.x += w0.x; a0.y += w0.y; a0.z += w0.z; a0.w += w0.w;
                    a1.x += w1.x; a1.y += w1.y; a1.z += w1.z; a1.w += w1.w;
                }
            }
            if (ANORM) {
                float4 n0 = *(const float4*)(pNW + koff);
                float4 n1 = *(const float4*)(pNW + koff + 4);
                a0.x *= rowsc * n0.x; a0.y *= rowsc * n0.y;
                a0.z *= rowsc * n0.z; a0.w *= rowsc * n0.w;
                a1.x *= rowsc * n1.x; a1.y *= rowsc * n1.y;
                a1.z *= rowsc * n1.z; a1.w *= rowsc * n1.w;
            }
            As[buf][lr][lc8 + 0] = f2tf32(a0.x); As[buf][lr][lc8 + 1] = f2tf32(a0.y);
            As[buf][lr][lc8 + 2] = f2tf32(a0.z); As[buf][lr][lc8 + 3] = f2tf32(a0.w);
            As[buf][lr][lc8 + 4] = f2tf32(a1.x); As[buf][lr][lc8 + 5] = f2tf32(a1.y);
            As[buf][lr][lc8 + 6] = f2tf32(a1.z); As[buf][lr][lc8 + 7] = f2tf32(a1.w);
        }
        {
            float4 b0 = make_float4(0.f, 0.f, 0.f, 0.f);
            float4 b1 = make_float4(0.f, 0.f, 0.f, 0.f);
            if (colOK) {
                b0 = *(const float4*)(pW + koff);
                b1 = *(const float4*)(pW + koff + 4);
            }
            Bs[buf][lr][lc8 + 0] = f2tf32(b0.x); Bs[buf][lr][lc8 + 1] = f2tf32(b0.y);
            Bs[buf][lr][lc8 + 2] = f2tf32(b0.z); Bs[buf][lr][lc8 + 3] = f2tf32(b0.w);
            Bs[buf][lr][lc8 + 4] = f2tf32(b1.x); Bs[buf][lr][lc8 + 5] = f2tf32(b1.y);
            Bs[buf][lr][lc8 + 6] = f2tf32(b1.z); Bs[buf][lr][lc8 + 7] = f2tf32(b1.w);
        }
    };

    float acc[2][4][4];
#pragma unroll
    for (int mi = 0; mi < 2; mi++)
#pragma unroll
        for (int ni = 0; ni < 4; ni++)
#pragma unroll
            for (int u = 0; u < 4; u++) acc[mi][ni][u] = 0.f;

    load_tile(0, 0);
    __syncthreads();

    for (int c = 0; c < nk; c++) {
        int cur = c & 1, nxt = cur ^ 1;
        if (c + 1 < nk) load_tile((c + 1) * TBK, nxt);
#pragma unroll
        for (int c2 = 0; c2 < 2; c2++) {
            uint32_t af[2][4], bf[4][2];
#pragma unroll
            for (int mi = 0; mi < 2; mi++) {
                int r = wm * 32 + mi * 16 + qr;
                af[mi][0] = As[cur][r][c2 * 8 + qc];
                af[mi][1] = As[cur][r + 8][c2 * 8 + qc];
                af[mi][2] = As[cur][r][c2 * 8 + 4 + qc];
                af[mi][3] = As[cur][r + 8][c2 * 8 + 4 + qc];
            }
#pragma unroll
            for (int ni = 0; ni < 4; ni++) {
                int n = wn * 32 + ni * 8 + qr;
                bf[ni][0] = Bs[cur][n][c2 * 8 + qc];
                bf[ni][1] = Bs[cur][n][c2 * 8 + 4 + qc];
            }
#pragma unroll
            for (int mi = 0; mi < 2; mi++)
#pragma unroll
                for (int ni = 0; ni < 4; ni++)
                    mma_tf32(acc[mi][ni], af[mi], bf[ni]);
        }
        __syncthreads();
    }

    if (TRANSC) {
        __shared__ float stage[TBN][68];
#pragma unroll
        for (int mi = 0; mi < 2; mi++) {
#pragma unroll
            for (int ni = 0; ni < 4; ni++) {
                int r0 = wm * 32 + mi * 16 + qr;
                int c0 = wn * 32 + ni * 8 + 2 * qc;
#pragma unroll
                for (int u = 0; u < 4; u++) {
                    int rl = r0 + (u >= 2 ? 8 : 0);
                    int cl = c0 + (u & 1);
                    float v = acc[mi][ni][u];
                    if (EPI == 1) v = softplusf(v + bias[colBase + cl]);
                    stage[cl][rl] = v;
                }
            }
        }
        __syncthreads();
#pragma unroll
        for (int it = 0; it < 8; it++) {
            int item = it * 128 + tid;
            int col = item >> 4;
            int r = (item & 15) * 4;
            int row = rowBase + r;
            if (row < M) {
                float4 v = *(const float4*)&stage[col][r];
                *(float4*)&C[(long)(colBase + col) * ldc + row] = v;
            }
        }
    } else {
#pragma unroll
        for (int mi = 0; mi < 2; mi++) {
#pragma unroll
            for (int ni = 0; ni < 4; ni++) {
                int r0 = rowBase + wm * 32 + mi * 16 + qr;
                int c0 = colBase + wn * 32 + ni * 8 + 2 * qc;
#pragma unroll
                for (int u = 0; u < 4; u++) {
                    int row = r0 + (u >= 2 ? 8 : 0);
                    int col = c0 + (u & 1);
                    if (row >= M || col >= N) continue;
                    float v = acc[mi][ni][u];
                    if (EPI == 1) {
                        v = softplusf(v + bias[col]);
                    } else if (EPI == 2) {
                        if (ks == 0) {
                            int tl = row % LSEQ;
                            int t = tl / NPATCH, p = tl % NPATCH;
                            v += bias[col] + pos[p * DM + col] + temp[t * DM + col];
                        }
                    }
                    if (ATOMIC) atomicAdd(&C[(long)row * ldc + col], v);
                    else        C[(long)row * ldc + col] = v;
                }
            }
        }
    }
}

// ---------------- slim residual add + rms scale + zero g_xz -------------------
__global__ void __launch_bounds__(128)
addnorm_kernel(int first) {
    int wid = threadIdx.x >> 5, lane = threadIdx.x & 31;
    int n = blockIdx.x * 4 + wid;
    {
        int gt = blockIdx.x * 128 + threadIdx.x;
        float4* xzp = (float4*)g_xz;
        float4 zero = make_float4(0.f, 0.f, 0.f, 0.f);
#pragma unroll
        for (int i = 0; i < 8; i++) xzp[(long)i * 50176 + gt] = zero;
    }

    const float4* hp = (const float4*)(g_hidden + (long)n * DM);
    float4* rp = (float4*)(g_resid + (long)n * DM);
    float4 h0 = hp[lane], h1 = hp[32 + lane];
    if (!first) {
        float4 r0 = rp[lane], r1 = rp[32 + lane];
        h0.x += r0.x; h0.y += r0.y; h0.z += r0.z; h0.w += r0.w;
        h1.x += r1.x; h1.y += r1.y; h1.z += r1.z; h1.w += r1.w;
    }
    rp[lane] = h0; rp[32 + lane] = h1;
    float ss = h0.x*h0.x + h0.y*h0.y + h0.z*h0.z + h0.w*h0.w
             + h1.x*h1.x + h1.y*h1.y + h1.z*h1.z + h1.w*h1.w;
#pragma unroll
    for (int m = 16; m; m >>= 1) ss += __shfl_xor_sync(0xffffffffu, ss, m);
    if (lane == 0) g_scale[n] = rsqrtf(ss / (float)DM + 1e-5f);
}

// ---------------- conv + silu + transpose  (and z-gate transpose) -------------
#define CT 64
#define CD 32
__global__ void __launch_bounds__(256)
conv_kernel(const float* __restrict__ cwf, const float* __restrict__ cbf,
            const float* __restrict__ cwb, const float* __restrict__ cbb) {
    {
        int bid = (blockIdx.z * gridDim.y + blockIdx.y) * gridDim.x + blockIdx.x;
        int gid = bid * 256 + threadIdx.x;
        const int NH4 = NT * DM / 4;          // 100352
        const int ND4 = 2 * NT * 48 / 4;      // 37632
        if (gid < NH4) ((float4*)g_hidden)[gid] = make_float4(0.f, 0.f, 0.f, 0.f);
        else if (gid < NH4 + ND4) ((float4*)g_dbl)[gid - NH4] = make_float4(0.f, 0.f, 0.f, 0.f);
    }
    __shared__ float tile[CT + 3][CD + 1];
    int mode = blockIdx.z / BB;
    int b = blockIdx.z % BB;
    int t0 = blockIdx.x * CT;
    int d0 = blockIdx.y * CD;
    int tid = threadIdx.x;
    int colbase = (mode == 2 ? DI : 0) + d0;

    int rr = tid >> 3, cc = (tid & 7) * 4;
#pragma unroll
    for (int it = 0; it < 3; it++) {
        int r = it * 32 + rr;
        if (r < CT + 3) {
            int ss = t0 - 3 + r;
            float4 v = make_float4(0.f, 0.f, 0.f, 0.f);
            if (ss >= 0 && ss < LSEQ) {
                int src = (mode == 1) ? (LSEQ - 1 - ss) : ss;
                v = *(const float4*)&g_xz[(long)(b * LSEQ + src) * (2 * DI) + colbase + cc];
            }
            tile[r][cc + 0] = v.x; tile[r][cc + 1] = v.y;
            tile[r][cc + 2] = v.z; tile[r][cc + 3] = v.w;
        }
    }
    __syncthreads();

    int tl = tid & 63, dg = tid >> 6;
    int tt = t0 + tl;
    if (tt >= LSEQ) return;
    if (mode == 2) {
#pragma unroll
        for (int i = 0; i < 8; i++) {
            int dl = dg * 8 + i;
            float v = siluf(tile[tl + 3][dl]);
            g_gz[(long)(d0 + dl) * NT + b * LSEQ + tt] = v;
        }
    } else {
        const float* cw = mode ? cwb : cwf;
        const float* cb = mode ? cbb : cbf;
#pragma unroll
        for (int i = 0; i < 8; i++) {
            int dl = dg * 8 + i;
            int d = d0 + dl;
            float acc = cb[d];
#pragma unroll
            for (int k = 0; k < 4; k++)
                acc = fmaf(tile[tl + k][dl], cw[d * 4 + k], acc);
            g_xs[((long)mode * DI + d) * NT + b * LSEQ + tt] = siluf(acc);
        }
    }
}

// ---------------- chunked SSM scan (two-pass, transposed inputs) --------------
// pass1 launched for chunks 0..NCHUNK-2 only (last chunk's summary is unused).
__global__ void scan_pass1_kernel(int layer) {
    int dir = blockIdx.z;
    int c = blockIdx.y;
    int tid = threadIdx.x;
    int grp = tid >> 4, s = tid & 15;
    int ch = blockIdx.x * 16 + grp;
    int b = ch >> 9, d = ch & (DI - 1);
    int e = ((dir * BB + b) * DI + d) * DSTATE + s;

    const float A_ds = g_A[(dir * NDEPTH + layer) * DI * DSTATE + d * DSTATE + s];
    long base = ((long)dir * DI + d) * NT + b * LSEQ;
    const float* dtp = g_dt + base;
    const float* xsp = g_xs + base;
    const float* dblp = g_dbl + ((long)dir * NT + b * LSEQ) * 48;

    float P = 1.f, q = 0.f;
    int t0 = c * CLEN;
    for (int tb = 0; tb < CLEN; tb += 16) {
        int tt = t0 + tb;
        float dtv = dtp[tt + s];
        float uv  = xsp[tt + s];
#pragma unroll
        for (int j = 0; j < 16; j++) {
            float dt = __shfl_sync(0xffffffffu, dtv, j, 16);
            float u  = __shfl_sync(0xffffffffu, uv,  j, 16);
            float Bv = dblp[(tt + j) * 48 + 16 + s];
            float a = __expf(dt * A_ds);
            P *= a;
            q = fmaf(a, q, (dt * u) * Bv);
        }
    }
    g_P[c][e] = P;
    g_q[c][e] = q;
}

__global__ void scan_pass2_kernel(int layer, const float* __restrict__ Dsf,
                                  const float* __restrict__ Dsb) {
    int dir = blockIdx.z;
    int c = blockIdx.y;
    int tid = threadIdx.x;
    int grp = tid >> 4, s = tid & 15;
    int ch = blockIdx.x * 16 + grp;
    int b = ch >> 9, d = ch & (DI - 1);
    int e = ((dir * BB + b) * DI + d) * DSTATE + s;

    const float A_ds = g_A[(dir * NDEPTH + layer) * DI * DSTATE + d * DSTATE + s];
    const float Dd = (dir ? Dsb : Dsf)[d];
    long base = ((long)dir * DI + d) * NT + b * LSEQ;
    const float* dtp = g_dt + base;
    const float* xsp = g_xs + base;
    const float* dblp = g_dbl + ((long)dir * NT + b * LSEQ) * 48;
    const float* gzp = g_gz + (long)d * NT + b * LSEQ;
    float* yp = g_y + base;

    float h = 0.f;
    for (int cc = 0; cc < c; cc++) h = fmaf(g_P[cc][e], h, g_q[cc][e]);

    int t0 = c * CLEN;
    float yb0 = 0.f, yb1 = 0.f, yb2 = 0.f;
    for (int tb = 0; tb < CLEN; tb += 16) {
        int tt = t0 + tb;
        float dtv = dtp[tt + s];
        float uv  = xsp[tt + s];
#pragma unroll
        for (int j = 0; j < 16; j++) {
            int ss = tt + j;
            float dt = __shfl_sync(0xffffffffu, dtv, j, 16);
            float u  = __shfl_sync(0xffffffffu, uv,  j, 16);
            float Bv = dblp[ss * 48 + 16 + s];
            float Cv = dblp[ss * 48 + 32 + s];
            float a = __expf(dt * A_ds);
            h = fmaf(a, h, (dt * u) * Bv);
            float p = h * Cv;
            p += __shfl_xor_sync(0xffffffffu, p, 8);
            p += __shfl_xor_sync(0xffffffffu, p, 4);
            p += __shfl_xor_sync(0xffffffffu, p, 2);
            p += __shfl_xor_sync(0xffffffffu, p, 1);
            if (s == 0) {
                int orig = dir ? (LSEQ - 1 - ss) : ss;
                float val = (p + Dd * u) * gzp[orig];
                if ((j & 3) == 0) yb0 = val;
                else if ((j & 3) == 1) yb1 = val;
                else if ((j & 3) == 2) yb2 = val;
                else {
                    float4 o = dir ? make_float4(val, yb2, yb1, yb0)
                                   : make_float4(yb0, yb1, yb2, val);
                    int addr = dir ? (LSEQ - 1 - ss) : (ss - 3);
                    *(float4*)&yp[addr] = o;
                }
            }
        }
    }
}

// ---------------- heads (with fused final rmsnorm) ----------------------------
__global__ void heads_kernel(const float* __restrict__ normf_w,
                             const float* __restrict__ bw1, const float* __restrict__ bb1,
                             const float* __restrict__ bw2, const float* __restrict__ bb2,
                             const float* __restrict__ pw1, const float* __restrict__ pb1,
                             const float* __restrict__ pw2, const float* __restrict__ pb2,
                             float* __restrict__ out) {
    int h = blockIdx.x;
    int b = blockIdx.y;
    int tid = threadIdx.x;
    __shared__ float sin_[DM];
    __shared__ float hidv[DM];
    __shared__ float sw[8];

    int n = b * LSEQ + h;
    float r = g_resid[n * DM + tid] + g_hidden[n * DM + tid];
    float ss = r * r;
#pragma unroll
    for (int m = 16; m; m >>= 1) ss += __shfl_xor_sync(0xffffffffu, ss, m);
    if ((tid & 31) == 0) sw[tid >> 5] = ss;
    __syncthreads();
    float tot = 0.f;
#pragma unroll
    for (int i = 0; i < 8; i++) tot += sw[i];
    float sc = rsqrtf(tot / (float)DM + 1e-5f);
    sin_[tid] = r * sc * normf_w[tid];
    __syncthreads();

    const float *w1, *b1, *w2, *b2;
    int nout; bool sig;
    if (h == 0) { w1 = bw1; b1 = bb1; w2 = bw2; b2 = bb2; nout = 3; sig = false; }
    else {
        int i = h - 1;
        w1 = pw1 + (long)i * DM * DM; b1 = pb1 + i * DM;
        w2 = pw2 + i * 2 * DM;        b2 = pb2 + i * 2;
        nout = 2; sig = true;
    }
    float acc = b1[tid];
    for (int k = 0; k < DM; k++) acc = fmaf(sin_[k], w1[(long)tid * DM + k], acc);
    hidv[tid] = fmaxf(acc, 0.f);
    __syncthreads();

    int w = tid >> 5, lane = tid & 31;
    if (w < nout) {
        float a = 0.f;
        for (int k = lane; k < DM; k += 32) a += hidv[k] * w2[w * DM + k];
#pragma unroll
        for (int m = 16; m; m >>= 1) a += __shfl_xor_sync(0xffffffffu, a, m);
        if (lane == 0) {
            float v = a + b2[w];
            if (sig) v = 1.f / (1.f + __expf(-v));
            int o = (h == 0) ? (b * 11 + w) : (b * 11 + 3 + (h - 1) * 2 + w);
            out[o] = v;
        }
    }
}

// ---------------- host side ----------------
extern "C" void kernel_launch(void* const* d_in, const int* in_sizes, int n_in,
                              void* d_out, int out_size) {
    (void)in_sizes; (void)n_in; (void)out_size;
    const float* x        = (const float*)d_in[0];
    const float* patch_w  = (const float*)d_in[1];
    const float* patch_b  = (const float*)d_in[2];
    const float* pos      = (const float*)d_in[3];
    const float* temp     = (const float*)d_in[4];
    const float* in_proj  = (const float*)d_in[5];
    const float* convf_w  = (const float*)d_in[6];
    const float* convf_b  = (const float*)d_in[7];
    const float* xprojf   = (const float*)d_in[8];
    const float* dtf_w    = (const float*)d_in[9];
    const float* dtf_b    = (const float*)d_in[10];
    const float* A_logf   = (const float*)d_in[11];
    const float* Dsf      = (const float*)d_in[12];
    const float* convb_w  = (const float*)d_in[13];
    const float* convb_b  = (const float*)d_in[14];
    const float* xprojb   = (const float*)d_in[15];
    const float* dtb_w    = (const float*)d_in[16];
    const float* dtb_b    = (const float*)d_in[17];
    const float* A_logb   = (const float*)d_in[18];
    const float* Dsb      = (const float*)d_in[19];
    const float* out_proj = (const float*)d_in[20];
    const float* norm_w   = (const float*)d_in[21];
    const float* normf_w  = (const float*)d_in[22];
    const float* bbox_w1  = (const float*)d_in[23];
    const float* bbox_b1  = (const float*)d_in[24];
    const float* bbox_w2  = (const float*)d_in[25];
    const float* bbox_b2  = (const float*)d_in[26];
    const float* pix_w1   = (const float*)d_in[27];
    const float* pix_b1   = (const float*)d_in[28];
    const float* pix_w2   = (const float*)d_in[29];
    const float* pix_b2   = (const float*)d_in[30];
    float* out = (float*)d_out;

    float *p_im2col, *p_hidden, *p_resid, *p_xz, *p_xs, *p_dbl, *p_dt, *p_y;
    cudaGetSymbolAddress((void**)&p_im2col, g_im2col);
    cudaGetSymbolAddress((void**)&p_hidden, g_hidden);
    cudaGetSymbolAddress((void**)&p_resid,  g_resid);
    cudaGetSymbolAddress((void**)&p_xz,     g_xz);
    cudaGetSymbolAddress((void**)&p_xs,     g_xs);
    cudaGetSymbolAddress((void**)&p_dbl,    g_dbl);
    cudaGetSymbolAddress((void**)&p_dt,     g_dt);
    cudaGetSymbolAddress((void**)&p_y,      g_y);

    const int GY = (NT + TBM - 1) / TBM;   // 25

    im2col_kernel<<<(NT * KPATCH + 255) / 256, 256>>>(x, A_logf, A_logb);

    // patch embed: N=256, K=768, split-K 8, atomic, EPI=2 -> 800 blocks
    mma_gemm_kernel<2, true, false, false, false><<<dim3(4, GY, 8), 128>>>(
        p_im2col, nullptr, KPATCH, patch_w, nullptr, p_hidden, DM,
        NT, DM, KPATCH, 8, patch_b, nullptr, pos, temp, 0, 0, nullptr);

    for (int i = 0; i < NDEPTH; i++) {
        addnorm_kernel<<<NT / 4, 128>>>(i == 0);
        // in_proj: ANORM, N=1024, K=256, split-K 2, atomic -> 800 blocks
        mma_gemm_kernel<0, true, false, false, true><<<dim3(16, GY, 2), 128>>>(
            p_resid, nullptr, DM, in_proj + (long)i * 2 * DI * DM, nullptr,
            p_xz, 2 * DI, NT, 2 * DI, DM, 2, nullptr, nullptr, nullptr, nullptr, 0, 0,
            norm_w + i * DM);
        // conv + silu + transpose (fwd, bwd, z-gate); zeroes hidden & dbl
        conv_kernel<<<dim3((LSEQ + CT - 1) / CT, DI / CD, 3 * BB), 256>>>(
            convf_w + (long)i * DI * 4, convf_b + i * DI,
            convb_w + (long)i * DI * 4, convb_b + i * DI);
        // xproj: TRANSA, N=48, K=512, dirs 2, split-K 16, atomic -> 800 blocks
        mma_gemm_kernel<0, true, true, false, false><<<dim3(1, GY, 32), 128>>>(
            p_xs, nullptr, NT, xprojf + (long)i * 48 * DI, xprojb + (long)i * 48 * DI,
            p_dbl, 48, NT, 48, DI, 16, nullptr, nullptr, nullptr, nullptr,
            (long)DI * NT, (long)NT * 48, nullptr);
        // dt: N=512, K=16, dirs 2, softplus, TRANSC -> dt_T (400 blocks)
        mma_gemm_kernel<1, false, false, true, false><<<dim3(8, GY, 2), 128>>>(
            p_dbl, nullptr, 48, dtf_w + (long)i * DI * DTR, dtb_w + (long)i * DI * DTR,
            p_dt, NT, NT, DI, DTR, 1, dtf_b + i * DI, dtb_b + i * DI, nullptr, nullptr,
            (long)NT * 48, (long)DI * NT, nullptr);
        // pass1 skips last chunk (summary unused)
        scan_pass1_kernel<<<dim3(64, NCHUNK - 1, 2), 256>>>(i);
        scan_pass2_kernel<<<dim3(64, NCHUNK, 2), 256>>>(i, Dsf + i * DI, Dsb + i * DI);
        // out_proj: TRANSA, N=256, K=512, split-K 8, atomic -> 800 blocks
        mma_gemm_kernel<0, true, true, false, false><<<dim3(4, GY, 8), 128>>>(
            p_y, p_y + (long)DI * NT, NT, out_proj + (long)i * DM * DI, nullptr,
            p_hidden, DM, NT, DM, DI, 8, nullptr, nullptr, nullptr, nullptr, 0, 0, nullptr);
    }

    heads_kernel<<<dim3(5, BB), 256>>>(normf_w, bbox_w1, bbox_b1, bbox_w2, bbox_b2,
                                       pix_w1, pix_b1, pix_w2, pix_b2, out);
}